// round 2
// baseline (speedup 1.0000x reference)
#include <cuda_runtime.h>
#include <cuda_bf16.h>

// Embedding gather: out[i, :] = table[ids[i], :]
// ids: int32 [4096*200] (JAX x64 disabled demotes int64->int32),
// table: f32 [1_000_000, 32], out: f32 [4096*200, 32]
// One float4 (16B) per thread; 8 consecutive threads cover one 128B row
// -> one coalesced 128B transaction per table row, fully coalesced stores.

__global__ void __launch_bounds__(256)
embedding_gather_kernel(const int* __restrict__ ids,
                        const float4* __restrict__ table4,
                        float4* __restrict__ out4,
                        int n4) {
    int i = blockIdx.x * blockDim.x + threadIdx.x;
    if (i >= n4) return;
    int row = i >> 3;        // which lookup
    int c   = i & 7;         // which float4 within the 32-float row
    int id = __ldg(&ids[row]);
    out4[i] = __ldg(&table4[(size_t)(unsigned)id * 8 + c]);
}

extern "C" void kernel_launch(void* const* d_in, const int* in_sizes, int n_in,
                              void* d_out, int out_size) {
    // Resolve inputs by element count: table has 32,000,000 f32 elements,
    // ids has 819,200 elements. Robust to metadata ordering.
    const void* p0 = d_in[0];
    const void* p1 = d_in[1];
    const int*    ids;
    const float4* table;
    int n_rows;
    if (in_sizes[0] > in_sizes[1]) {
        table = (const float4*)p0;
        ids   = (const int*)p1;
        n_rows = in_sizes[1];
    } else {
        ids   = (const int*)p0;
        table = (const float4*)p1;
        n_rows = in_sizes[0];
    }

    float4* out = (float4*)d_out;
    int n4 = n_rows * 8;               // float4 elements in output
    int threads = 256;
    int blocks = (n4 + threads - 1) / threads;
    embedding_gather_kernel<<<blocks, threads>>>(ids, table, out, n4);
}

// round 4
// speedup vs baseline: 1.2210x; 1.2210x over previous
#include <cuda_runtime.h>
#include <cuda_bf16.h>

// Embedding gather: out[i, :] = table[ids[i], :]
// ids: int32 [819200], table: f32 [1e6, 32] (128 MB ~ L2 size), out: f32 [819200, 32]
//
//  - table loads use an L2::evict_last cache policy (keep table L2-resident)
//  - output stores use .cs streaming (write-once; don't evict the table)
//  - 2 independent row-gathers per thread for memory-level parallelism

__device__ __forceinline__ float4 ldg_table(const float4* p, unsigned long long pol) {
    float4 v;
    asm volatile("ld.global.nc.L2::cache_hint.v4.f32 {%0,%1,%2,%3}, [%4], %5;"
                 : "=f"(v.x), "=f"(v.y), "=f"(v.z), "=f"(v.w)
                 : "l"(p), "l"(pol));
    return v;
}

__device__ __forceinline__ void stg_stream(float4* p, float4 v) {
    asm volatile("st.global.cs.v4.f32 [%0], {%1,%2,%3,%4};"
                 :: "l"(p), "f"(v.x), "f"(v.y), "f"(v.z), "f"(v.w)
                 : "memory");
}

__global__ void __launch_bounds__(256)
embedding_gather_kernel(const int* __restrict__ ids,
                        const float4* __restrict__ table4,
                        float4* __restrict__ out4,
                        int half) {
    int i = blockIdx.x * blockDim.x + threadIdx.x;
    if (i >= half) return;
    int j = i + half;

    unsigned long long pol;
    asm volatile("createpolicy.fractional.L2::evict_last.b64 %0, 1.0;" : "=l"(pol));

    int row0 = i >> 3, c0 = i & 7;
    int row1 = j >> 3, c1 = j & 7;

    // Two independent id loads, then two independent gathers in flight.
    int id0 = __ldg(&ids[row0]);
    int id1 = __ldg(&ids[row1]);

    float4 v0 = ldg_table(&table4[(size_t)(unsigned)id0 * 8 + c0], pol);
    float4 v1 = ldg_table(&table4[(size_t)(unsigned)id1 * 8 + c1], pol);

    stg_stream(&out4[i], v0);
    stg_stream(&out4[j], v1);
}

extern "C" void kernel_launch(void* const* d_in, const int* in_sizes, int n_in,
                              void* d_out, int out_size) {
    // Resolve inputs by element count (table: 32,000,000 f32; ids: 819,200).
    const int*    ids;
    const float4* table;
    int n_rows;
    if (in_sizes[0] > in_sizes[1]) {
        table = (const float4*)d_in[0];
        ids   = (const int*)d_in[1];
        n_rows = in_sizes[1];
    } else {
        ids   = (const int*)d_in[0];
        table = (const float4*)d_in[1];
        n_rows = in_sizes[0];
    }

    float4* out = (float4*)d_out;
    int n4 = n_rows * 8;        // total float4 elements in output (even)
    int half = n4 >> 1;
    int threads = 256;
    int blocks = (half + threads - 1) / threads;
    embedding_gather_kernel<<<blocks, threads>>>(ids, table, out, half);
}

// round 5
// speedup vs baseline: 1.3205x; 1.0815x over previous
#include <cuda_runtime.h>
#include <cuda_bf16.h>

// Embedding gather: out[i, :] = table[ids[i], :]
// ids: int32 [819200], table: f32 [1e6, 32] (128 MB ~ L2 size), out: f32 [819200, 32]
//
//  - table loads use an L2::evict_last cache policy (keep table L2-resident)
//  - output stores use .cs streaming (write-once; don't evict the table)
//  - 4 independent row-gathers per thread for memory-level parallelism

__device__ __forceinline__ float4 ldg_table(const float4* p, unsigned long long pol) {
    float4 v;
    asm volatile("ld.global.nc.L2::cache_hint.v4.f32 {%0,%1,%2,%3}, [%4], %5;"
                 : "=f"(v.x), "=f"(v.y), "=f"(v.z), "=f"(v.w)
                 : "l"(p), "l"(pol));
    return v;
}

__device__ __forceinline__ void stg_stream(float4* p, float4 v) {
    asm volatile("st.global.cs.v4.f32 [%0], {%1,%2,%3,%4};"
                 :: "l"(p), "f"(v.x), "f"(v.y), "f"(v.z), "f"(v.w)
                 : "memory");
}

__global__ void __launch_bounds__(256)
embedding_gather_kernel(const int* __restrict__ ids,
                        const float4* __restrict__ table4,
                        float4* __restrict__ out4,
                        int quarter) {
    int i = blockIdx.x * blockDim.x + threadIdx.x;
    if (i >= quarter) return;

    unsigned long long pol;
    asm volatile("createpolicy.fractional.L2::evict_last.b64 %0, 1.0;" : "=l"(pol));

    int i0 = i;
    int i1 = i + quarter;
    int i2 = i + 2 * quarter;
    int i3 = i + 3 * quarter;

    // Four independent id loads, then four independent gathers in flight.
    int id0 = __ldg(&ids[i0 >> 3]);
    int id1 = __ldg(&ids[i1 >> 3]);
    int id2 = __ldg(&ids[i2 >> 3]);
    int id3 = __ldg(&ids[i3 >> 3]);

    float4 v0 = ldg_table(&table4[(size_t)(unsigned)id0 * 8 + (i0 & 7)], pol);
    float4 v1 = ldg_table(&table4[(size_t)(unsigned)id1 * 8 + (i1 & 7)], pol);
    float4 v2 = ldg_table(&table4[(size_t)(unsigned)id2 * 8 + (i2 & 7)], pol);
    float4 v3 = ldg_table(&table4[(size_t)(unsigned)id3 * 8 + (i3 & 7)], pol);

    stg_stream(&out4[i0], v0);
    stg_stream(&out4[i1], v1);
    stg_stream(&out4[i2], v2);
    stg_stream(&out4[i3], v3);
}

extern "C" void kernel_launch(void* const* d_in, const int* in_sizes, int n_in,
                              void* d_out, int out_size) {
    // Resolve inputs by element count (table: 32,000,000 f32; ids: 819,200).
    const int*    ids;
    const float4* table;
    int n_rows;
    if (in_sizes[0] > in_sizes[1]) {
        table = (const float4*)d_in[0];
        ids   = (const int*)d_in[1];
        n_rows = in_sizes[1];
    } else {
        ids   = (const int*)d_in[0];
        table = (const float4*)d_in[1];
        n_rows = in_sizes[0];
    }

    float4* out = (float4*)d_out;
    int n4 = n_rows * 8;          // total float4 elements in output (divisible by 4)
    int quarter = n4 >> 2;
    int threads = 256;
    int blocks = (quarter + threads - 1) / threads;
    embedding_gather_kernel<<<blocks, threads>>>(ids, table, out, quarter);
}